// round 1
// baseline (speedup 1.0000x reference)
#include <cuda_runtime.h>
#include <math.h>
#include <float.h>

#define Bb 2
#define Ss 2048
#define Nn 1024
#define Hh 1024
#define NHh 16
#define Dd 64

// Scratch (allocation-free rule: __device__ globals)
__device__ float g_q[Bb * Ss * Hh];     // projected Q  [B,S,H]
__device__ float g_k[Bb * Nn * Hh];     // projected K  [B,N,H]
__device__ float g_v[Bb * Nn * Hh];     // projected V  [B,N,H]
__device__ float g_ao[Bb * Ss * Hh];    // attention out [B,S,H]
__device__ float g_vmean[Bb * Hh];      // mean over N of V, per (b, h*D+d)

// ---------------------------------------------------------------------------
// Y[m,n] = sum_k X[m,k] * W[n,k]   (x @ W.T), K = Nout = 1024
// 64x64 block tile, K-tile 32, 256 threads, 4x4 micro-tile.
// ---------------------------------------------------------------------------
__global__ __launch_bounds__(256) void linear_kernel(
    const float* __restrict__ X, const float* __restrict__ W,
    float* __restrict__ Y)
{
    const int K = 1024;
    __shared__ float Xs[64][33];
    __shared__ float Ws[64][33];

    int tid = threadIdx.x;
    int ty = tid >> 4;        // 0..15
    int tx = tid & 15;        // 0..15
    int m0 = blockIdx.y * 64;
    int n0 = blockIdx.x * 64;

    int lr = tid >> 3;        // 0..31  (loader row)
    int lc = (tid & 7) * 4;   // 0..28  (loader k-col, float4)

    float acc[4][4];
#pragma unroll
    for (int i = 0; i < 4; i++)
#pragma unroll
        for (int j = 0; j < 4; j++) acc[i][j] = 0.f;

    for (int k0 = 0; k0 < K; k0 += 32) {
        float4 x0 = *(const float4*)(X + (size_t)(m0 + lr) * K + k0 + lc);
        float4 x1 = *(const float4*)(X + (size_t)(m0 + lr + 32) * K + k0 + lc);
        float4 w0 = *(const float4*)(W + (size_t)(n0 + lr) * K + k0 + lc);
        float4 w1 = *(const float4*)(W + (size_t)(n0 + lr + 32) * K + k0 + lc);
        Xs[lr][lc + 0] = x0.x; Xs[lr][lc + 1] = x0.y; Xs[lr][lc + 2] = x0.z; Xs[lr][lc + 3] = x0.w;
        Xs[lr + 32][lc + 0] = x1.x; Xs[lr + 32][lc + 1] = x1.y; Xs[lr + 32][lc + 2] = x1.z; Xs[lr + 32][lc + 3] = x1.w;
        Ws[lr][lc + 0] = w0.x; Ws[lr][lc + 1] = w0.y; Ws[lr][lc + 2] = w0.z; Ws[lr][lc + 3] = w0.w;
        Ws[lr + 32][lc + 0] = w1.x; Ws[lr + 32][lc + 1] = w1.y; Ws[lr + 32][lc + 2] = w1.z; Ws[lr + 32][lc + 3] = w1.w;
        __syncthreads();

#pragma unroll
        for (int kk = 0; kk < 32; kk++) {
            float a[4], b[4];
#pragma unroll
            for (int i = 0; i < 4; i++) a[i] = Xs[ty * 4 + i][kk];
#pragma unroll
            for (int j = 0; j < 4; j++) b[j] = Ws[tx * 4 + j][kk];
#pragma unroll
            for (int i = 0; i < 4; i++)
#pragma unroll
                for (int j = 0; j < 4; j++) acc[i][j] = fmaf(a[i], b[j], acc[i][j]);
        }
        __syncthreads();
    }

#pragma unroll
    for (int i = 0; i < 4; i++)
#pragma unroll
        for (int j = 0; j < 4; j++)
            Y[(size_t)(m0 + ty * 4 + i) * 1024 + (n0 + tx * 4 + j)] = acc[i][j];
}

// ---------------------------------------------------------------------------
// v_mean[b, hd] = (1/N) * sum_n V[b, n, hd]
// ---------------------------------------------------------------------------
__global__ void vmean_kernel(const float* __restrict__ V, float* __restrict__ vm)
{
    int idx = blockIdx.x * blockDim.x + threadIdx.x;   // 0 .. B*H-1
    if (idx >= Bb * Hh) return;
    int b = idx >> 10;
    int hd = idx & 1023;
    const float* p = V + (size_t)b * Nn * Hh + hd;
    float s = 0.f;
    for (int n = 0; n < Nn; n++) s += p[(size_t)n * Hh];
    vm[idx] = s * (1.0f / Nn);
}

// ---------------------------------------------------------------------------
// Fused prefix-masked flash attention.
// Grid: (S/64, NH, B). Block: 256 threads. 64 queries x D=64 per CTA.
// block_ends is sorted, so the visible set per query t is a prefix; we early
// exit the KV loop when the tile's first end exceeds the tile's max t.
// Rows with zero visible blocks get v_mean (matches reference's finfo.min
// uniform-softmax behavior).
// ---------------------------------------------------------------------------
__global__ __launch_bounds__(256) void flash_kernel(
    const float* __restrict__ Q, const float* __restrict__ Kp,
    const float* __restrict__ Vp, const int* __restrict__ be,
    const float* __restrict__ vmean, float* __restrict__ O)
{
    __shared__ float Qs[64][68];
    __shared__ float Ks[64][68];
    __shared__ float Vs[64][68];
    __shared__ float Ps[64][68];
    __shared__ int   bes[64];

    int tid = threadIdx.x;
    int b = blockIdx.z;
    int h = blockIdx.y;
    int t0 = blockIdx.x * 64;

    const float* Qg = Q + ((size_t)b * Ss + t0) * Hh + h * Dd;
    const float* Kg = Kp + (size_t)b * Nn * Hh + h * Dd;
    const float* Vg = Vp + (size_t)b * Nn * Hh + h * Dd;

    // Load Q tile (64 rows x 64 cols), float4
    {
        int f = tid;
#pragma unroll
        for (int it = 0; it < 4; it++, f += 256) {
            int r = f >> 4;
            int c = (f & 15) * 4;
            *(float4*)(&Qs[r][c]) = *(const float4*)(Qg + (size_t)r * Hh + c);
        }
    }

    int ty = tid >> 4;
    int tx = tid & 15;
    int i0 = ty * 4;
    int c0 = tx * 4;

    float m_i[4], l_i[4], acc[4][4];
#pragma unroll
    for (int i = 0; i < 4; i++) {
        m_i[i] = -FLT_MAX;
        l_i[i] = 0.f;
#pragma unroll
        for (int j = 0; j < 4; j++) acc[i][j] = 0.f;
    }

    const int tmax = t0 + 63;
    const float sc = 0.125f;   // 1/sqrt(D)

    for (int n0 = 0; n0 < Nn; n0 += 64) {
        __syncthreads();   // protect Ps/Vs/Ks/bes from previous iteration readers
        if (tid < 64) bes[tid] = be[n0 + tid];
        {
            int f = tid;
#pragma unroll
            for (int it = 0; it < 4; it++, f += 256) {
                int r = f >> 4;
                int c = (f & 15) * 4;
                *(float4*)(&Ks[r][c]) = *(const float4*)(Kg + (size_t)(n0 + r) * Hh + c);
                *(float4*)(&Vs[r][c]) = *(const float4*)(Vg + (size_t)(n0 + r) * Hh + c);
            }
        }
        __syncthreads();

        if (bes[0] > tmax) break;   // sorted ends: tile (and all later ones) invisible

        // S = Q K^T  (4x4 micro-tile per thread)
        float s[4][4];
#pragma unroll
        for (int i = 0; i < 4; i++)
#pragma unroll
            for (int j = 0; j < 4; j++) s[i][j] = 0.f;
#pragma unroll
        for (int d = 0; d < 64; d++) {
            float a[4], kb[4];
#pragma unroll
            for (int i = 0; i < 4; i++) a[i] = Qs[i0 + i][d];
#pragma unroll
            for (int j = 0; j < 4; j++) kb[j] = Ks[c0 + j][d];
#pragma unroll
            for (int i = 0; i < 4; i++)
#pragma unroll
                for (int j = 0; j < 4; j++) s[i][j] = fmaf(a[i], kb[j], s[i][j]);
        }

        // online softmax update, row-wise (row spread over the 16 tx lanes)
#pragma unroll
        for (int i = 0; i < 4; i++) {
            int t = t0 + i0 + i;
            bool vis[4];
            float sv[4];
            float rm = -FLT_MAX;
#pragma unroll
            for (int j = 0; j < 4; j++) {
                vis[j] = (bes[c0 + j] <= t);
                sv[j] = vis[j] ? s[i][j] * sc : -FLT_MAX;
                rm = fmaxf(rm, sv[j]);
            }
#pragma unroll
            for (int o = 8; o; o >>= 1)
                rm = fmaxf(rm, __shfl_xor_sync(0xffffffffu, rm, o));
            float nm = fmaxf(m_i[i], rm);
            float p[4];
            float rl = 0.f;
#pragma unroll
            for (int j = 0; j < 4; j++) {
                p[j] = vis[j] ? __expf(sv[j] - nm) : 0.f;
                rl += p[j];
            }
#pragma unroll
            for (int o = 8; o; o >>= 1)
                rl += __shfl_xor_sync(0xffffffffu, rl, o);
            float alpha = __expf(m_i[i] - nm);   // both -FLT_MAX -> exp(0)=1, acc=0 anyway
            m_i[i] = nm;
            l_i[i] = l_i[i] * alpha + rl;
#pragma unroll
            for (int j = 0; j < 4; j++) acc[i][j] *= alpha;
            Ps[i0 + i][c0 + 0] = p[0];
            Ps[i0 + i][c0 + 1] = p[1];
            Ps[i0 + i][c0 + 2] = p[2];
            Ps[i0 + i][c0 + 3] = p[3];
        }
        __syncthreads();

        // acc += P @ V  (4x4 micro-tile; cols are d-dims now)
#pragma unroll
        for (int jj = 0; jj < 64; jj++) {
            float pa[4], vb[4];
#pragma unroll
            for (int i = 0; i < 4; i++) pa[i] = Ps[i0 + i][jj];
#pragma unroll
            for (int c = 0; c < 4; c++) vb[c] = Vs[jj][c0 + c];
#pragma unroll
            for (int i = 0; i < 4; i++)
#pragma unroll
                for (int c = 0; c < 4; c++) acc[i][c] = fmaf(pa[i], vb[c], acc[i][c]);
        }
    }

    // epilogue
    float* Og = O + ((size_t)b * Ss + t0) * Hh + h * Dd;
#pragma unroll
    for (int i = 0; i < 4; i++) {
        bool uni = (l_i[i] == 0.f);
        float inv = uni ? 0.f : (1.f / l_i[i]);
#pragma unroll
        for (int c = 0; c < 4; c++) {
            float val = uni ? vmean[b * Hh + h * Dd + c0 + c] : acc[i][c] * inv;
            Og[(size_t)(i0 + i) * Hh + (c0 + c)] = val;
        }
    }
}

// ---------------------------------------------------------------------------
extern "C" void kernel_launch(void* const* d_in, const int* in_sizes, int n_in,
                              void* d_out, int out_size)
{
    const float* token_q  = (const float*)d_in[0];
    const float* block_kv = (const float*)d_in[1];
    const int*   blk_ends = (const int*)d_in[2];
    const float* Wq       = (const float*)d_in[3];
    const float* Wk       = (const float*)d_in[4];
    const float* Wv       = (const float*)d_in[5];
    const float* Wo       = (const float*)d_in[6];
    float* out = (float*)d_out;

    float *q, *k, *v, *ao, *vm;
    cudaGetSymbolAddress((void**)&q,  g_q);
    cudaGetSymbolAddress((void**)&k,  g_k);
    cudaGetSymbolAddress((void**)&v,  g_v);
    cudaGetSymbolAddress((void**)&ao, g_ao);
    cudaGetSymbolAddress((void**)&vm, g_vmean);

    // Projections: Q (M=B*S=4096), K,V (M=B*N=2048)
    linear_kernel<<<dim3(16, (Bb * Ss) / 64), 256>>>(token_q, Wq, q);
    linear_kernel<<<dim3(16, (Bb * Nn) / 64), 256>>>(block_kv, Wk, k);
    linear_kernel<<<dim3(16, (Bb * Nn) / 64), 256>>>(block_kv, Wv, v);

    vmean_kernel<<<(Bb * Hh + 255) / 256, 256>>>(v, vm);

    flash_kernel<<<dim3(Ss / 64, NHh, Bb), 256>>>(q, k, v, blk_ends, vm, ao);

    // Output projection
    linear_kernel<<<dim3(16, (Bb * Ss) / 64), 256>>>(ao, Wo, out);
}

// round 2
// speedup vs baseline: 1.3377x; 1.3377x over previous
#include <cuda_runtime.h>
#include <math.h>
#include <float.h>
#include <stdint.h>

#define Bb 2
#define Ss 2048
#define Nn 1024
#define Hh 1024
#define NHh 16
#define Dd 64

// Scratch (allocation-free rule: __device__ globals)
__device__ float g_q[Bb * Ss * Hh];     // projected Q  [B,S,H]
__device__ float g_k[Bb * Nn * Hh];     // projected K  [B,N,H]
__device__ float g_v[Bb * Nn * Hh];     // projected V  [B,N,H]
__device__ float g_ao[Bb * Ss * Hh];    // attention out [B,S,H]
__device__ float g_vmean[Bb * Hh];      // mean over N of V, per (b, h*D+d)
__device__ float g_vpart[8][Bb * Hh];   // partial sums for vmean

__device__ __forceinline__ float f2tf32(float x) {
    uint32_t u;
    asm("cvt.rna.tf32.f32 %0, %1;" : "=r"(u) : "f"(x));
    return __uint_as_float(u);
}

// ---------------------------------------------------------------------------
// Y[m,n] = sum_k X[m,k] * W[n,k]  (x @ W.T), K = 1024, N = 1024.
// tf32 mma.sync m16n8k8. CTA tile 128x128, K-tile 32, 256 threads (8 warps),
// warp tile 32x64 (2 m16 x 8 n8 fragments).
// ---------------------------------------------------------------------------
__global__ __launch_bounds__(256) void linear_tf32_kernel(
    const float* __restrict__ X, const float* __restrict__ W,
    float* __restrict__ Y)
{
    const int K = 1024;
    __shared__ float As[128][36];   // pitch 36 words = 144B (16B aligned rows)
    __shared__ float Bs[128][36];

    int tid  = threadIdx.x;
    int wid  = tid >> 5;
    int lane = tid & 31;
    int m0 = blockIdx.y * 128;
    int n0 = blockIdx.x * 128;

    int warp_m = (wid >> 1) * 32;   // 0,32,64,96
    int warp_n = (wid & 1) * 64;    // 0,64

    int lr = tid >> 3;              // 0..31 loader row
    int lc = (tid & 7) * 4;         // 0..28 loader k-col

    float acc[2][8][4];
#pragma unroll
    for (int mi = 0; mi < 2; mi++)
#pragma unroll
        for (int ni = 0; ni < 8; ni++)
#pragma unroll
            for (int r = 0; r < 4; r++) acc[mi][ni][r] = 0.f;

    const int gr = lane >> 2;       // 0..7
    const int gc = lane & 3;        // 0..3

    for (int k0 = 0; k0 < K; k0 += 32) {
#pragma unroll
        for (int rr = 0; rr < 4; rr++) {
            int r = lr + rr * 32;
            float4 xa = *(const float4*)(X + (size_t)(m0 + r) * K + k0 + lc);
            float4 wb = *(const float4*)(W + (size_t)(n0 + r) * K + k0 + lc);
            As[r][lc + 0] = f2tf32(xa.x); As[r][lc + 1] = f2tf32(xa.y);
            As[r][lc + 2] = f2tf32(xa.z); As[r][lc + 3] = f2tf32(xa.w);
            Bs[r][lc + 0] = f2tf32(wb.x); Bs[r][lc + 1] = f2tf32(wb.y);
            Bs[r][lc + 2] = f2tf32(wb.z); Bs[r][lc + 3] = f2tf32(wb.w);
        }
        __syncthreads();

#pragma unroll
        for (int ks = 0; ks < 4; ks++) {
            int kb = ks * 8;
            uint32_t a[2][4];
#pragma unroll
            for (int mi = 0; mi < 2; mi++) {
                int r = warp_m + mi * 16 + gr;
                int c = kb + gc;
                a[mi][0] = __float_as_uint(As[r][c]);
                a[mi][1] = __float_as_uint(As[r + 8][c]);
                a[mi][2] = __float_as_uint(As[r][c + 4]);
                a[mi][3] = __float_as_uint(As[r + 8][c + 4]);
            }
            uint32_t b[8][2];
#pragma unroll
            for (int ni = 0; ni < 8; ni++) {
                int n = warp_n + ni * 8 + gr;
                int c = kb + gc;
                b[ni][0] = __float_as_uint(Bs[n][c]);
                b[ni][1] = __float_as_uint(Bs[n][c + 4]);
            }
#pragma unroll
            for (int mi = 0; mi < 2; mi++)
#pragma unroll
                for (int ni = 0; ni < 8; ni++) {
                    asm volatile(
                        "mma.sync.aligned.m16n8k8.row.col.f32.tf32.tf32.f32 "
                        "{%0,%1,%2,%3}, {%4,%5,%6,%7}, {%8,%9}, {%0,%1,%2,%3};\n"
                        : "+f"(acc[mi][ni][0]), "+f"(acc[mi][ni][1]),
                          "+f"(acc[mi][ni][2]), "+f"(acc[mi][ni][3])
                        : "r"(a[mi][0]), "r"(a[mi][1]), "r"(a[mi][2]), "r"(a[mi][3]),
                          "r"(b[ni][0]), "r"(b[ni][1]));
                }
        }
        __syncthreads();
    }

    // epilogue
#pragma unroll
    for (int mi = 0; mi < 2; mi++) {
#pragma unroll
        for (int ni = 0; ni < 8; ni++) {
            int row = m0 + warp_m + mi * 16 + gr;
            int col = n0 + warp_n + ni * 8 + gc * 2;
            Y[(size_t)row * 1024 + col]           = acc[mi][ni][0];
            Y[(size_t)row * 1024 + col + 1]       = acc[mi][ni][1];
            Y[(size_t)(row + 8) * 1024 + col]     = acc[mi][ni][2];
            Y[(size_t)(row + 8) * 1024 + col + 1] = acc[mi][ni][3];
        }
    }
}

// ---------------------------------------------------------------------------
// vmean: split N into 8 chunks for parallelism, then reduce.
// ---------------------------------------------------------------------------
__global__ void vmean_part_kernel(const float* __restrict__ V, float* __restrict__ vp)
{
    int idx = blockIdx.x * blockDim.x + threadIdx.x;   // 0 .. B*H-1
    int chunk = blockIdx.y;                            // 0..7
    if (idx >= Bb * Hh) return;
    int b = idx >> 10;
    int hd = idx & 1023;
    const float* p = V + (size_t)b * Nn * Hh + hd + (size_t)chunk * (Nn / 8) * Hh;
    float s = 0.f;
#pragma unroll 4
    for (int n = 0; n < Nn / 8; n++) s += p[(size_t)n * Hh];
    vp[chunk * (Bb * Hh) + idx] = s;
}

__global__ void vmean_reduce_kernel(const float* __restrict__ vp, float* __restrict__ vm)
{
    int idx = blockIdx.x * blockDim.x + threadIdx.x;
    if (idx >= Bb * Hh) return;
    float s = 0.f;
#pragma unroll
    for (int c = 0; c < 8; c++) s += vp[c * (Bb * Hh) + idx];
    vm[idx] = s * (1.0f / Nn);
}

// ---------------------------------------------------------------------------
// Fused prefix-masked flash attention (fp32, unchanged this round).
// ---------------------------------------------------------------------------
__global__ __launch_bounds__(256) void flash_kernel(
    const float* __restrict__ Q, const float* __restrict__ Kp,
    const float* __restrict__ Vp, const int* __restrict__ be,
    const float* __restrict__ vmean, float* __restrict__ O)
{
    __shared__ float Qs[64][68];
    __shared__ float Ks[64][68];
    __shared__ float Vs[64][68];
    __shared__ float Ps[64][68];
    __shared__ int   bes[64];

    int tid = threadIdx.x;
    int b = blockIdx.z;
    int h = blockIdx.y;
    int t0 = blockIdx.x * 64;

    const float* Qg = Q + ((size_t)b * Ss + t0) * Hh + h * Dd;
    const float* Kg = Kp + (size_t)b * Nn * Hh + h * Dd;
    const float* Vg = Vp + (size_t)b * Nn * Hh + h * Dd;

    {
        int f = tid;
#pragma unroll
        for (int it = 0; it < 4; it++, f += 256) {
            int r = f >> 4;
            int c = (f & 15) * 4;
            *(float4*)(&Qs[r][c]) = *(const float4*)(Qg + (size_t)r * Hh + c);
        }
    }

    int ty = tid >> 4;
    int tx = tid & 15;
    int i0 = ty * 4;
    int c0 = tx * 4;

    float m_i[4], l_i[4], acc[4][4];
#pragma unroll
    for (int i = 0; i < 4; i++) {
        m_i[i] = -FLT_MAX;
        l_i[i] = 0.f;
#pragma unroll
        for (int j = 0; j < 4; j++) acc[i][j] = 0.f;
    }

    const int tmax = t0 + 63;
    const float sc = 0.125f;

    for (int n0 = 0; n0 < Nn; n0 += 64) {
        __syncthreads();
        if (tid < 64) bes[tid] = be[n0 + tid];
        {
            int f = tid;
#pragma unroll
            for (int it = 0; it < 4; it++, f += 256) {
                int r = f >> 4;
                int c = (f & 15) * 4;
                *(float4*)(&Ks[r][c]) = *(const float4*)(Kg + (size_t)(n0 + r) * Hh + c);
                *(float4*)(&Vs[r][c]) = *(const float4*)(Vg + (size_t)(n0 + r) * Hh + c);
            }
        }
        __syncthreads();

        if (bes[0] > tmax) break;

        float s[4][4];
#pragma unroll
        for (int i = 0; i < 4; i++)
#pragma unroll
            for (int j = 0; j < 4; j++) s[i][j] = 0.f;
#pragma unroll
        for (int d = 0; d < 64; d++) {
            float a[4], kb[4];
#pragma unroll
            for (int i = 0; i < 4; i++) a[i] = Qs[i0 + i][d];
#pragma unroll
            for (int j = 0; j < 4; j++) kb[j] = Ks[c0 + j][d];
#pragma unroll
            for (int i = 0; i < 4; i++)
#pragma unroll
                for (int j = 0; j < 4; j++) s[i][j] = fmaf(a[i], kb[j], s[i][j]);
        }

#pragma unroll
        for (int i = 0; i < 4; i++) {
            int t = t0 + i0 + i;
            bool vis[4];
            float sv[4];
            float rm = -FLT_MAX;
#pragma unroll
            for (int j = 0; j < 4; j++) {
                vis[j] = (bes[c0 + j] <= t);
                sv[j] = vis[j] ? s[i][j] * sc : -FLT_MAX;
                rm = fmaxf(rm, sv[j]);
            }
#pragma unroll
            for (int o = 8; o; o >>= 1)
                rm = fmaxf(rm, __shfl_xor_sync(0xffffffffu, rm, o));
            float nm = fmaxf(m_i[i], rm);
            float p[4];
            float rl = 0.f;
#pragma unroll
            for (int j = 0; j < 4; j++) {
                p[j] = vis[j] ? __expf(sv[j] - nm) : 0.f;
                rl += p[j];
            }
#pragma unroll
            for (int o = 8; o; o >>= 1)
                rl += __shfl_xor_sync(0xffffffffu, rl, o);
            float alpha = __expf(m_i[i] - nm);
            m_i[i] = nm;
            l_i[i] = l_i[i] * alpha + rl;
#pragma unroll
            for (int j = 0; j < 4; j++) acc[i][j] *= alpha;
            Ps[i0 + i][c0 + 0] = p[0];
            Ps[i0 + i][c0 + 1] = p[1];
            Ps[i0 + i][c0 + 2] = p[2];
            Ps[i0 + i][c0 + 3] = p[3];
        }
        __syncthreads();

#pragma unroll
        for (int jj = 0; jj < 64; jj++) {
            float pa[4], vb[4];
#pragma unroll
            for (int i = 0; i < 4; i++) pa[i] = Ps[i0 + i][jj];
#pragma unroll
            for (int c = 0; c < 4; c++) vb[c] = Vs[jj][c0 + c];
#pragma unroll
            for (int i = 0; i < 4; i++)
#pragma unroll
                for (int c = 0; c < 4; c++) acc[i][c] = fmaf(pa[i], vb[c], acc[i][c]);
        }
    }

    float* Og = O + ((size_t)b * Ss + t0) * Hh + h * Dd;
#pragma unroll
    for (int i = 0; i < 4; i++) {
        bool uni = (l_i[i] == 0.f);
        float inv = uni ? 0.f : (1.f / l_i[i]);
#pragma unroll
        for (int c = 0; c < 4; c++) {
            float val = uni ? vmean[b * Hh + h * Dd + c0 + c] : acc[i][c] * inv;
            Og[(size_t)(i0 + i) * Hh + (c0 + c)] = val;
        }
    }
}

// ---------------------------------------------------------------------------
extern "C" void kernel_launch(void* const* d_in, const int* in_sizes, int n_in,
                              void* d_out, int out_size)
{
    const float* token_q  = (const float*)d_in[0];
    const float* block_kv = (const float*)d_in[1];
    const int*   blk_ends = (const int*)d_in[2];
    const float* Wq       = (const float*)d_in[3];
    const float* Wk       = (const float*)d_in[4];
    const float* Wv       = (const float*)d_in[5];
    const float* Wo       = (const float*)d_in[6];
    float* out = (float*)d_out;

    float *q, *k, *v, *ao, *vm, *vp;
    cudaGetSymbolAddress((void**)&q,  g_q);
    cudaGetSymbolAddress((void**)&k,  g_k);
    cudaGetSymbolAddress((void**)&v,  g_v);
    cudaGetSymbolAddress((void**)&ao, g_ao);
    cudaGetSymbolAddress((void**)&vm, g_vmean);
    cudaGetSymbolAddress((void**)&vp, g_vpart);

    // Projections (tf32 tensor path): Q (M=4096), K,V (M=2048)
    linear_tf32_kernel<<<dim3(8, (Bb * Ss) / 128), 256>>>(token_q, Wq, q);
    linear_tf32_kernel<<<dim3(8, (Bb * Nn) / 128), 256>>>(block_kv, Wk, k);
    linear_tf32_kernel<<<dim3(8, (Bb * Nn) / 128), 256>>>(block_kv, Wv, v);

    vmean_part_kernel<<<dim3((Bb * Hh + 255) / 256, 8), 256>>>(v, vp);
    vmean_reduce_kernel<<<(Bb * Hh + 255) / 256, 256>>>(vp, vm);

    flash_kernel<<<dim3(Ss / 64, NHh, Bb), 256>>>(q, k, v, blk_ends, vm, ao);

    // Output projection
    linear_tf32_kernel<<<dim3(8, (Bb * Ss) / 128), 256>>>(ao, Wo, out);
}

// round 3
// speedup vs baseline: 3.5285x; 2.6378x over previous
#include <cuda_runtime.h>
#include <math.h>
#include <float.h>
#include <stdint.h>

#define Bb 2
#define Ss 2048
#define Nn 1024
#define Hh 1024
#define NHh 16
#define Dd 64

// Scratch (__device__ globals: allocation-free rule)
__device__ float g_q[Bb * Ss * Hh];
__device__ float g_k[Bb * Nn * Hh];
__device__ float g_v[Bb * Nn * Hh];
__device__ float g_ao[Bb * Ss * Hh];
__device__ float g_tq[Bb * Ss * Hh];    // tf32-rounded token_q
__device__ float g_kvr[Bb * Nn * Hh];   // tf32-rounded block_kv
__device__ float g_wq[Hh * Hh];
__device__ float g_wk[Hh * Hh];
__device__ float g_wv[Hh * Hh];
__device__ float g_wo[Hh * Hh];
__device__ float g_vmean[Bb * Hh];
__device__ float g_vpart[16][Bb * Hh];

__device__ __forceinline__ float f2tf32(float x) {
    uint32_t u;
    asm("cvt.rna.tf32.f32 %0, %1;" : "=r"(u) : "f"(x));
    return __uint_as_float(u);
}

__device__ __forceinline__ void cp16(void* smem, const void* g) {
    uint32_t s = (uint32_t)__cvta_generic_to_shared(smem);
    asm volatile("cp.async.cg.shared.global [%0], [%1], 16;" :: "r"(s), "l"(g));
}

// ---------------------------------------------------------------------------
// Elementwise tf32 rounding pass (n multiple of 4)
// ---------------------------------------------------------------------------
__global__ void round_tf32_kernel(const float* __restrict__ x, float* __restrict__ y, int n)
{
    int i = (blockIdx.x * blockDim.x + threadIdx.x) * 4;
    if (i >= n) return;
    float4 v = *(const float4*)(x + i);
    float4 r;
    r.x = f2tf32(v.x); r.y = f2tf32(v.y); r.z = f2tf32(v.z); r.w = f2tf32(v.w);
    *(float4*)(y + i) = r;
}

// ---------------------------------------------------------------------------
// Y[m,n] = sum_k X[m,k] * W[n,k], K=N=1024. Inputs pre-rounded to tf32.
// 128x128 CTA tile, K-tile 32, 256 threads, warp tile 32x64, cp.async 2-stage.
// gridDim.z==2 selects (Wa,Ya)/(Wb,Yb) to merge K/V projections in one wave.
// ---------------------------------------------------------------------------
__global__ __launch_bounds__(256) void gemm_tf32(
    const float* __restrict__ X,
    const float* __restrict__ Wa, float* __restrict__ Ya,
    const float* __restrict__ Wb, float* __restrict__ Yb)
{
    const float* W = (blockIdx.z == 0) ? Wa : Wb;
    float* Y = (blockIdx.z == 0) ? Ya : Yb;
    const int K = 1024;
    __shared__ float As[2][128][36];
    __shared__ float Bs[2][128][36];

    int tid = threadIdx.x;
    int wid = tid >> 5;
    int lane = tid & 31;
    int m0 = blockIdx.y * 128;
    int n0 = blockIdx.x * 128;
    int warp_m = (wid >> 1) * 32;
    int warp_n = (wid & 1) * 64;
    int lr = tid >> 3;
    int lc = (tid & 7) * 4;
    const int gr = lane >> 2;
    const int gc = lane & 3;

    float acc[2][8][4];
#pragma unroll
    for (int mi = 0; mi < 2; mi++)
#pragma unroll
        for (int ni = 0; ni < 8; ni++)
#pragma unroll
            for (int r = 0; r < 4; r++) acc[mi][ni][r] = 0.f;

    // prologue: stage 0
#pragma unroll
    for (int rr = 0; rr < 4; rr++) {
        int r = lr + rr * 32;
        cp16(&As[0][r][lc], X + (size_t)(m0 + r) * K + lc);
        cp16(&Bs[0][r][lc], W + (size_t)(n0 + r) * K + lc);
    }
    asm volatile("cp.async.commit_group;" ::: "memory");

    for (int kt = 0; kt < 32; kt++) {
        int cur = kt & 1;
        if (kt < 31) {
            int k0 = (kt + 1) * 32;
            int nxt = cur ^ 1;
#pragma unroll
            for (int rr = 0; rr < 4; rr++) {
                int r = lr + rr * 32;
                cp16(&As[nxt][r][lc], X + (size_t)(m0 + r) * K + k0 + lc);
                cp16(&Bs[nxt][r][lc], W + (size_t)(n0 + r) * K + k0 + lc);
            }
            asm volatile("cp.async.commit_group;" ::: "memory");
            asm volatile("cp.async.wait_group 1;" ::: "memory");
        } else {
            asm volatile("cp.async.wait_group 0;" ::: "memory");
        }
        __syncthreads();

#pragma unroll
        for (int ks = 0; ks < 4; ks++) {
            int kb = ks * 8;
            uint32_t a[2][4];
#pragma unroll
            for (int mi = 0; mi < 2; mi++) {
                int r = warp_m + mi * 16 + gr;
                int c = kb + gc;
                a[mi][0] = __float_as_uint(As[cur][r][c]);
                a[mi][1] = __float_as_uint(As[cur][r + 8][c]);
                a[mi][2] = __float_as_uint(As[cur][r][c + 4]);
                a[mi][3] = __float_as_uint(As[cur][r + 8][c + 4]);
            }
            uint32_t b[8][2];
#pragma unroll
            for (int ni = 0; ni < 8; ni++) {
                int n = warp_n + ni * 8 + gr;
                int c = kb + gc;
                b[ni][0] = __float_as_uint(Bs[cur][n][c]);
                b[ni][1] = __float_as_uint(Bs[cur][n][c + 4]);
            }
#pragma unroll
            for (int mi = 0; mi < 2; mi++)
#pragma unroll
                for (int ni = 0; ni < 8; ni++) {
                    asm volatile(
                        "mma.sync.aligned.m16n8k8.row.col.f32.tf32.tf32.f32 "
                        "{%0,%1,%2,%3}, {%4,%5,%6,%7}, {%8,%9}, {%0,%1,%2,%3};\n"
                        : "+f"(acc[mi][ni][0]), "+f"(acc[mi][ni][1]),
                          "+f"(acc[mi][ni][2]), "+f"(acc[mi][ni][3])
                        : "r"(a[mi][0]), "r"(a[mi][1]), "r"(a[mi][2]), "r"(a[mi][3]),
                          "r"(b[ni][0]), "r"(b[ni][1]));
                }
        }
        __syncthreads();
    }

#pragma unroll
    for (int mi = 0; mi < 2; mi++) {
#pragma unroll
        for (int ni = 0; ni < 8; ni++) {
            int row = m0 + warp_m + mi * 16 + gr;
            int col = n0 + warp_n + ni * 8 + gc * 2;
            *(float2*)&Y[(size_t)row * 1024 + col] = make_float2(acc[mi][ni][0], acc[mi][ni][1]);
            *(float2*)&Y[(size_t)(row + 8) * 1024 + col] = make_float2(acc[mi][ni][2], acc[mi][ni][3]);
        }
    }
}

// ---------------------------------------------------------------------------
// vmean (16-way N split + reduce)
// ---------------------------------------------------------------------------
__global__ void vmean_part_kernel(const float* __restrict__ V, float* __restrict__ vp)
{
    int idx = blockIdx.x * blockDim.x + threadIdx.x;
    int chunk = blockIdx.y;
    if (idx >= Bb * Hh) return;
    int b = idx >> 10;
    int hd = idx & 1023;
    const float* p = V + (size_t)b * Nn * Hh + hd + (size_t)chunk * (Nn / 16) * Hh;
    float s = 0.f;
#pragma unroll 4
    for (int n = 0; n < Nn / 16; n++) s += p[(size_t)n * Hh];
    vp[chunk * (Bb * Hh) + idx] = s;
}

__global__ void vmean_reduce_kernel(const float* __restrict__ vp, float* __restrict__ vm)
{
    int idx = blockIdx.x * blockDim.x + threadIdx.x;
    if (idx >= Bb * Hh) return;
    float s = 0.f;
#pragma unroll
    for (int c = 0; c < 16; c++) s += vp[c * (Bb * Hh) + idx];
    vm[idx] = s * (1.0f / Nn);
}

// ---------------------------------------------------------------------------
// Flash attention on tf32 mma.sync.
// CTA: 64 queries x D=64, 128 threads (4 warps), warp = 16 query rows.
// Output rounded to tf32 (it feeds the Wo GEMM).
// ---------------------------------------------------------------------------
__global__ __launch_bounds__(128) void flash_tf32_kernel(
    const float* __restrict__ Q, const float* __restrict__ Kp,
    const float* __restrict__ Vp, const int* __restrict__ be,
    const float* __restrict__ vmean, float* __restrict__ O)
{
    __shared__ float Qs[64][68];
    __shared__ float Ks[64][68];
    __shared__ float Vs[64][68];
    __shared__ float Ps[64][68];
    __shared__ int   bes[64];

    int tid = threadIdx.x;
    int wid = tid >> 5;
    int lane = tid & 31;
    const int gr = lane >> 2;
    const int gc = lane & 3;
    int b = blockIdx.z, h = blockIdx.y, t0 = blockIdx.x * 64;

    const float* Qg = Q + ((size_t)b * Ss + t0) * Hh + h * Dd;
    const float* Kg = Kp + (size_t)b * Nn * Hh + h * Dd;
    const float* Vg = Vp + (size_t)b * Nn * Hh + h * Dd;

    // Q load: scale by 1/sqrt(D)=0.125 (exact), round to tf32
#pragma unroll
    for (int p = 0; p < 8; p++) {
        int f = p * 128 + tid;
        int r = f >> 4, c = (f & 15) * 4;
        float4 x = *(const float4*)(Qg + (size_t)r * Hh + c);
        Qs[r][c + 0] = f2tf32(x.x * 0.125f);
        Qs[r][c + 1] = f2tf32(x.y * 0.125f);
        Qs[r][c + 2] = f2tf32(x.z * 0.125f);
        Qs[r][c + 3] = f2tf32(x.w * 0.125f);
    }

    const int rbase = wid * 16 + gr;     // rows rbase, rbase+8
    float m_i[2] = {-FLT_MAX, -FLT_MAX};
    float l_i[2] = {0.f, 0.f};
    float acc[8][4];
#pragma unroll
    for (int ni = 0; ni < 8; ni++)
#pragma unroll
        for (int r = 0; r < 4; r++) acc[ni][r] = 0.f;

    const int tmax = t0 + 63;

    for (int n0 = 0; n0 < Nn; n0 += 64) {
        __syncthreads();
        if (tid < 64) bes[tid] = be[n0 + tid];
#pragma unroll
        for (int p = 0; p < 8; p++) {
            int f = p * 128 + tid;
            int r = f >> 4, c = (f & 15) * 4;
            float4 kx = *(const float4*)(Kg + (size_t)(n0 + r) * Hh + c);
            float4 vx = *(const float4*)(Vg + (size_t)(n0 + r) * Hh + c);
            Ks[r][c + 0] = f2tf32(kx.x); Ks[r][c + 1] = f2tf32(kx.y);
            Ks[r][c + 2] = f2tf32(kx.z); Ks[r][c + 3] = f2tf32(kx.w);
            Vs[r][c + 0] = f2tf32(vx.x); Vs[r][c + 1] = f2tf32(vx.y);
            Vs[r][c + 2] = f2tf32(vx.z); Vs[r][c + 3] = f2tf32(vx.w);
        }
        __syncthreads();

        if (bes[0] > tmax) break;

        // S = Q K^T  (warp rows rbase.., 64 key cols)
        float s[8][4];
#pragma unroll
        for (int ni = 0; ni < 8; ni++)
#pragma unroll
            for (int r = 0; r < 4; r++) s[ni][r] = 0.f;
#pragma unroll
        for (int kb = 0; kb < 8; kb++) {
            int c = kb * 8;
            uint32_t a0 = __float_as_uint(Qs[rbase][c + gc]);
            uint32_t a1 = __float_as_uint(Qs[rbase + 8][c + gc]);
            uint32_t a2 = __float_as_uint(Qs[rbase][c + gc + 4]);
            uint32_t a3 = __float_as_uint(Qs[rbase + 8][c + gc + 4]);
#pragma unroll
            for (int ni = 0; ni < 8; ni++) {
                uint32_t b0 = __float_as_uint(Ks[ni * 8 + gr][c + gc]);
                uint32_t b1 = __float_as_uint(Ks[ni * 8 + gr][c + gc + 4]);
                asm volatile(
                    "mma.sync.aligned.m16n8k8.row.col.f32.tf32.tf32.f32 "
                    "{%0,%1,%2,%3}, {%4,%5,%6,%7}, {%8,%9}, {%0,%1,%2,%3};\n"
                    : "+f"(s[ni][0]), "+f"(s[ni][1]), "+f"(s[ni][2]), "+f"(s[ni][3])
                    : "r"(a0), "r"(a1), "r"(a2), "r"(a3), "r"(b0), "r"(b1));
            }
        }

        // per-thread bes for my 16 columns
        int bcol[8][2];
#pragma unroll
        for (int ni = 0; ni < 8; ni++) {
            bcol[ni][0] = bes[ni * 8 + gc * 2];
            bcol[ni][1] = bes[ni * 8 + gc * 2 + 1];
        }

        // online softmax, two row-halves (rbase, rbase+8)
#pragma unroll
        for (int half = 0; half < 2; half++) {
            int t = t0 + rbase + half * 8;
            float sv[8][2];
            float rm = -FLT_MAX;
#pragma unroll
            for (int ni = 0; ni < 8; ni++) {
                sv[ni][0] = (bcol[ni][0] <= t) ? s[ni][half * 2 + 0] : -FLT_MAX;
                sv[ni][1] = (bcol[ni][1] <= t) ? s[ni][half * 2 + 1] : -FLT_MAX;
                rm = fmaxf(rm, fmaxf(sv[ni][0], sv[ni][1]));
            }
            rm = fmaxf(rm, __shfl_xor_sync(0xffffffffu, rm, 1));
            rm = fmaxf(rm, __shfl_xor_sync(0xffffffffu, rm, 2));
            float nm = fmaxf(m_i[half], rm);
            float rl = 0.f;
            float pv[8][2];
#pragma unroll
            for (int ni = 0; ni < 8; ni++) {
                pv[ni][0] = (sv[ni][0] == -FLT_MAX) ? 0.f : __expf(sv[ni][0] - nm);
                pv[ni][1] = (sv[ni][1] == -FLT_MAX) ? 0.f : __expf(sv[ni][1] - nm);
                rl += pv[ni][0] + pv[ni][1];
            }
            rl += __shfl_xor_sync(0xffffffffu, rl, 1);
            rl += __shfl_xor_sync(0xffffffffu, rl, 2);
            float alpha = (m_i[half] == nm) ? 1.f : __expf(m_i[half] - nm);
            m_i[half] = nm;
            l_i[half] = l_i[half] * alpha + rl;
            int row = rbase + half * 8;
#pragma unroll
            for (int ni = 0; ni < 8; ni++) {
                acc[ni][half * 2 + 0] *= alpha;
                acc[ni][half * 2 + 1] *= alpha;
                Ps[row][ni * 8 + gc * 2]     = f2tf32(pv[ni][0]);
                Ps[row][ni * 8 + gc * 2 + 1] = f2tf32(pv[ni][1]);
            }
        }
        __syncwarp();   // P is warp-private (rows rbase..rbase+15 only)

        // acc += P @ V
#pragma unroll
        for (int kb = 0; kb < 8; kb++) {
            int c = kb * 8;
            uint32_t a0 = __float_as_uint(Ps[rbase][c + gc]);
            uint32_t a1 = __float_as_uint(Ps[rbase + 8][c + gc]);
            uint32_t a2 = __float_as_uint(Ps[rbase][c + gc + 4]);
            uint32_t a3 = __float_as_uint(Ps[rbase + 8][c + gc + 4]);
#pragma unroll
            for (int ni = 0; ni < 8; ni++) {
                uint32_t b0 = __float_as_uint(Vs[c + gc][ni * 8 + gr]);
                uint32_t b1 = __float_as_uint(Vs[c + gc + 4][ni * 8 + gr]);
                asm volatile(
                    "mma.sync.aligned.m16n8k8.row.col.f32.tf32.tf32.f32 "
                    "{%0,%1,%2,%3}, {%4,%5,%6,%7}, {%8,%9}, {%0,%1,%2,%3};\n"
                    : "+f"(acc[ni][0]), "+f"(acc[ni][1]), "+f"(acc[ni][2]), "+f"(acc[ni][3])
                    : "r"(a0), "r"(a1), "r"(a2), "r"(a3), "r"(b0), "r"(b1));
            }
        }
    }

    // epilogue (round output to tf32: it feeds the Wo GEMM)
    float* Og = O + ((size_t)b * Ss + t0) * Hh + h * Dd;
    const float* vmb = vmean + b * Hh + h * Dd;
#pragma unroll
    for (int half = 0; half < 2; half++) {
        int row = rbase + half * 8;
        bool uni = (l_i[half] == 0.f);
        float inv = uni ? 0.f : (1.f / l_i[half]);
#pragma unroll
        for (int ni = 0; ni < 8; ni++) {
            int col = ni * 8 + gc * 2;
            float o0 = uni ? vmb[col]     : acc[ni][half * 2 + 0] * inv;
            float o1 = uni ? vmb[col + 1] : acc[ni][half * 2 + 1] * inv;
            *(float2*)&Og[(size_t)row * Hh + col] = make_float2(f2tf32(o0), f2tf32(o1));
        }
    }
}

// ---------------------------------------------------------------------------
extern "C" void kernel_launch(void* const* d_in, const int* in_sizes, int n_in,
                              void* d_out, int out_size)
{
    const float* token_q  = (const float*)d_in[0];
    const float* block_kv = (const float*)d_in[1];
    const int*   blk_ends = (const int*)d_in[2];
    const float* Wq       = (const float*)d_in[3];
    const float* Wk       = (const float*)d_in[4];
    const float* Wv       = (const float*)d_in[5];
    const float* Wo       = (const float*)d_in[6];
    float* out = (float*)d_out;

    float *q, *k, *v, *ao, *vm, *vp, *tq, *kvr, *wq, *wk, *wv, *wo;
    cudaGetSymbolAddress((void**)&q,   g_q);
    cudaGetSymbolAddress((void**)&k,   g_k);
    cudaGetSymbolAddress((void**)&v,   g_v);
    cudaGetSymbolAddress((void**)&ao,  g_ao);
    cudaGetSymbolAddress((void**)&vm,  g_vmean);
    cudaGetSymbolAddress((void**)&vp,  g_vpart);
    cudaGetSymbolAddress((void**)&tq,  g_tq);
    cudaGetSymbolAddress((void**)&kvr, g_kvr);
    cudaGetSymbolAddress((void**)&wq,  g_wq);
    cudaGetSymbolAddress((void**)&wk,  g_wk);
    cudaGetSymbolAddress((void**)&wv,  g_wv);
    cudaGetSymbolAddress((void**)&wo,  g_wo);

    const int nTQ = Bb * Ss * Hh, nKV = Bb * Nn * Hh, nW = Hh * Hh;
    round_tf32_kernel<<<nTQ / 1024, 256>>>(token_q, tq, nTQ);
    round_tf32_kernel<<<nKV / 1024, 256>>>(block_kv, kvr, nKV);
    round_tf32_kernel<<<nW / 1024, 256>>>(Wq, wq, nW);
    round_tf32_kernel<<<nW / 1024, 256>>>(Wk, wk, nW);
    round_tf32_kernel<<<nW / 1024, 256>>>(Wv, wv, nW);
    round_tf32_kernel<<<nW / 1024, 256>>>(Wo, wo, nW);

    // Q projection (M=4096); K+V projections merged in one wave (M=2048, z=2)
    gemm_tf32<<<dim3(8, (Bb * Ss) / 128, 1), 256>>>(tq, wq, q, wq, q);
    gemm_tf32<<<dim3(8, (Bb * Nn) / 128, 2), 256>>>(kvr, wk, k, wv, v);

    vmean_part_kernel<<<dim3((Bb * Hh + 255) / 256, 16), 256>>>(v, vp);
    vmean_reduce_kernel<<<(Bb * Hh + 255) / 256, 256>>>(vp, vm);

    flash_tf32_kernel<<<dim3(Ss / 64, NHh, Bb), 128>>>(q, k, v, blk_ends, vm, ao);

    // Output projection
    gemm_tf32<<<dim3(8, (Bb * Ss) / 128, 1), 256>>>(ao, wo, out, wo, out);
}